// round 6
// baseline (speedup 1.0000x reference)
#include <cuda_runtime.h>
#include <math.h>

static constexpr int NIN   = 8192;   // inner dim for both layers
static constexpr int N_HID = 8192;
static constexpr int N_OUT = 1024;
static constexpr int SB    = 32;     // stats blocks (32*256 = 8192, one elem/thread)
static constexpr int TOTAL_BLOCKS = SB + N_HID + N_OUT;  // 9248

// ---------------- scratch (no allocations allowed) ----------------
__device__ float g_z[NIN];          // layer-1 z = exp(x)
__device__ float g_hidden[N_HID];   // layer-1 output
__device__ float g_w1sum[N_HID];    // W1 row sums
__device__ float g_w2sum[N_OUT];    // W2 row sums

// per-stats-block partials (plain stores; combined deterministically later)
__device__ float              g_psum[SB];
__device__ unsigned int       g_pmin[SB];   // order-preserving key, min
__device__ unsigned long long g_pmax[SB];   // (key<<32)|idx, max => last-argmax

// order-preserving float<->uint key
__device__ __forceinline__ unsigned int fkey(float v) {
    unsigned u = __float_as_uint(v);
    return (u & 0x80000000u) ? ~u : (u | 0x80000000u);
}
__device__ __forceinline__ float fdec(unsigned int k) {
    unsigned u = (k & 0x80000000u) ? (k ^ 0x80000000u) : ~k;
    return __uint_as_float(u);
}

// ---------------------------------------------------------------------------
// ONE streaming wave, zero cross-block sync:
//   bids [0,32)            : z = exp(x) + per-block stats partials
//   bids [32, 32+8192)     : W1 row sums -> g_w1sum
//   bids [32+8192, 9248)   : W2 row sums -> g_w2sum
// ---------------------------------------------------------------------------
__global__ void __launch_bounds__(256) big_kernel(const float* __restrict__ x,
                                                  const float* __restrict__ W1,
                                                  const float* __restrict__ W2)
{
    const int bid = blockIdx.x;
    const int tid = threadIdx.x;

    if (bid < SB) {
        // -------- stats partial block: one element per thread --------
        const int j = bid * 256 + tid;
        const float v = expf(x[j]);
        g_z[j] = v;

        __shared__ float              ss[256];
        __shared__ unsigned int       smn[256];
        __shared__ unsigned long long smx[256];
        ss[tid]  = v;
        const unsigned k = fkey(v);
        smn[tid] = k;
        smx[tid] = ((unsigned long long)k << 32) | (unsigned)j;
        __syncthreads();
        for (int o = 128; o > 0; o >>= 1) {
            if (tid < o) {
                ss[tid]  += ss[tid + o];
                smn[tid]  = min(smn[tid], smn[tid + o]);
                smx[tid]  = max(smx[tid], smx[tid + o]);
            }
            __syncthreads();
        }
        if (tid == 0) {
            g_psum[bid] = ss[0];
            g_pmin[bid] = smn[0];
            g_pmax[bid] = smx[0];
        }
        return;
    }

    // -------- row-sum block (the proven streaming loop) --------
    const int  rb   = bid - SB;
    const bool isW2 = (rb >= N_HID);
    const float* __restrict__ W = isW2 ? W2 : W1;
    const int  row  = isW2 ? (rb - N_HID) : rb;
    const float4* __restrict__ Wr =
        reinterpret_cast<const float4*>(W + (size_t)row * NIN);

    float acc = 0.f;
    #pragma unroll
    for (int i = 0; i < NIN / 4 / 256; ++i) {
        float4 v = __ldcs(Wr + tid + i * 256);
        acc += (v.x + v.y) + (v.z + v.w);
    }
    #pragma unroll
    for (int o = 16; o > 0; o >>= 1) acc += __shfl_down_sync(0xffffffffu, acc, o);

    __shared__ float swp[8];
    const int wid = tid >> 5, lane = tid & 31;
    if (lane == 0) swp[wid] = acc;
    __syncthreads();

    if (tid == 0) {
        float Wsum = 0.f;
        #pragma unroll
        for (int w = 0; w < 8; ++w) Wsum += swp[w];
        if (isW2) g_w2sum[row] = Wsum; else g_w1sum[row] = Wsum;
    }
}

// ---------------------------------------------------------------------------
// finaleA: combine the 32 stats partials (fixed order -> deterministic), then
// evaluate the layer-1 closed form for all 8192 rows: one row per thread,
// one independent scattered W1 load each, spread over 32 blocks.
// ---------------------------------------------------------------------------
__global__ void __launch_bounds__(256) finaleA_kernel(const float* __restrict__ W1)
{
    const int tid = threadIdx.x;
    __shared__ float s_Zsum, s_zmin, s_zmax;
    __shared__ int   s_jlast;

    if (tid == 0) {
        float sum = 0.f;
        unsigned mnk = 0xFFFFFFFFu;
        unsigned long long mx = 0ULL;
        #pragma unroll
        for (int i = 0; i < SB; ++i) {
            sum += g_psum[i];
            mnk  = min(mnk, g_pmin[i]);
            mx   = max(mx,  g_pmax[i]);
        }
        s_Zsum  = sum;
        s_zmin  = fdec(mnk);
        s_zmax  = fdec((unsigned)(mx >> 32));
        s_jlast = (int)(unsigned)mx;
    }
    __syncthreads();

    const float Zsum = s_Zsum, zmin = s_zmin, zmax = s_zmax;
    const int   jlast = s_jlast;

    const int r = blockIdx.x * 256 + tid;           // grid 32 x 256 = 8192 rows
    const float Wsum = g_w1sum[r];
    const float tmp = Wsum * Zsum / (Wsum - 1.f);
    float result = INFINITY;

    if (Wsum > 1.f) {
        if (zmin <= tmp) {                           // first mismatch at i=0 -> k = n-1
            float Wc = Wsum - W1[(size_t)r * NIN + jlast];
            float Zc = Zsum - zmax;
            result = Wc * Zc / (Wc - 1.f);
        }                                            // else: no mismatch -> inf
    } else {
        // rare general path (never taken for this data): serial row scan
        int cnt = 0; float sle = 0.f, wle = 0.f, m = -INFINITY; int jm = -1;
        for (int j = 0; j < NIN; ++j) {
            float zj = g_z[j];
            if (zj <= tmp) {
                cnt++; sle += zj; wle += W1[(size_t)r * NIN + j];
                if (zj > m || (zj == m && j > jm)) { m = zj; jm = j; }
            }
        }
        if (cnt == NIN) {
            // inf
        } else if (cnt == 0) {
            float Wc = Wsum - W1[(size_t)r * NIN + jlast];
            float Zc = Zsum - zmax;
            result = Wc * Zc / (Wc - 1.f);
        } else if (cnt - 1 != 0) {
            float Zc = sle - m;
            float Wc = wle - W1[(size_t)r * NIN + jm];
            result = Wc * Zc / (Wc - 1.f);
        }
    }
    g_hidden[r] = result;
}

// ---------------------------------------------------------------------------
// finaleB: ONE block of 1024 threads.
//   phase 1: stats over g_hidden (deterministic fixed-order tree)
//   phase 2: layer-2 closed form, one output row per thread
// ---------------------------------------------------------------------------
__global__ void __launch_bounds__(1024) finaleB_kernel(const float* __restrict__ W2,
                                                       float* __restrict__ out)
{
    const int tid = threadIdx.x;

    float sum = 0.f, mn = INFINITY, mx = -INFINITY;
    int jm = -1;
    #pragma unroll
    for (int i = 0; i < N_HID / 1024; ++i) {
        const int j = tid + i * 1024;
        float v = g_hidden[j];
        sum += v;
        mn = fminf(mn, v);
        if (v > mx || (v == mx && j > jm)) { mx = v; jm = j; }
    }
    __shared__ float ss[1024], smn[1024], smx[1024];
    __shared__ int   sj[1024];
    ss[tid] = sum; smn[tid] = mn; smx[tid] = mx; sj[tid] = jm;
    __syncthreads();
    for (int o = 512; o > 0; o >>= 1) {
        if (tid < o) {
            ss[tid]  += ss[tid + o];
            smn[tid]  = fminf(smn[tid], smn[tid + o]);
            float v2 = smx[tid + o]; int i2 = sj[tid + o];
            if (v2 > smx[tid] || (v2 == smx[tid] && i2 > sj[tid])) { smx[tid] = v2; sj[tid] = i2; }
        }
        __syncthreads();
    }
    const float Zsum = ss[0];
    const float zmin = smn[0];
    const float zmax = smx[0];
    const int   jlast = sj[0];
    __syncthreads();

    const int r = tid;
    if (r >= N_OUT) return;

    const float Wsum = g_w2sum[r];
    const float tmp = Wsum * Zsum / (Wsum - 1.f);
    float result = INFINITY;

    if (Wsum > 1.f) {
        if (zmin <= tmp) {
            float Wc = Wsum - W2[(size_t)r * NIN + jlast];
            float Zc = Zsum - zmax;
            result = Wc * Zc / (Wc - 1.f);
        }
    } else {
        // rare general path (never taken for this data): serial row scan
        int cnt = 0; float sle = 0.f, wle = 0.f, m = -INFINITY; int jmm = -1;
        for (int j = 0; j < NIN; ++j) {
            float zj = g_hidden[j];
            if (zj <= tmp) {
                cnt++; sle += zj; wle += W2[(size_t)r * NIN + j];
                if (zj > m || (zj == m && j > jmm)) { m = zj; jmm = j; }
            }
        }
        if (cnt == NIN) {
            // inf
        } else if (cnt == 0) {
            float Wc = Wsum - W2[(size_t)r * NIN + jlast];
            float Zc = Zsum - zmax;
            result = Wc * Zc / (Wc - 1.f);
        } else if (cnt - 1 != 0) {
            float Zc = sle - m;
            float Wc = wle - W2[(size_t)r * NIN + jmm];
            result = Wc * Zc / (Wc - 1.f);
        }
    }
    out[r] = result;
}

extern "C" void kernel_launch(void* const* d_in, const int* in_sizes, int n_in,
                              void* d_out, int out_size)
{
    const float* x  = (const float*)d_in[0];
    const float* W1 = (const float*)d_in[1];
    const float* W2 = (const float*)d_in[2];
    float* out = (float*)d_out;

    big_kernel<<<TOTAL_BLOCKS, 256>>>(x, W1, W2);  // exp/stats partials + all row sums
    finaleA_kernel<<<32, 256>>>(W1);               // combine stats + layer-1 closed form
    finaleB_kernel<<<1, 1024>>>(W2, out);          // hidden stats + layer-2
}